// round 7
// baseline (speedup 1.0000x reference)
#include <cuda_runtime.h>
#include <math.h>

#define T_NO   200
#define SUBN   20
#define E_NOC  2000
#define I_NOC  500
#define T_DATA 10000
#define COS_NO 17
#define BW     32                       // recurrence block size
#define NBLK   ((T_DATA + BW - 1) / BW) // 313

// ---------------- device scratch (static allocation only) ----------------
__device__ float g_se[T_DATA * SUBN];
__device__ float g_si[T_DATA * SUBN];
__device__ float g_syn[T_DATA * SUBN];    // filtered drive + Theta folded in
__device__ float g_sv[T_DATA * SUBN];     // raw pre-activation
__device__ float g_ek[SUBN * T_NO];
__device__ float g_ik[SUBN * T_NO];
__device__ float g_spkk[SUBN * T_NO];
__device__ float g_histk[SUBN * T_NO];
__device__ float g_lutn[SUBN * 800];      // nibble LUT: [s][i=0..49][n=0..15]
__device__ int   g_idx_e[E_NOC];
__device__ int   g_idx_i[I_NOC];

// ---------------- K0: indices + kernels + nibble LUT + filter output ----------------
__global__ void prep_kernel(const float* __restrict__ C_syn_e,
                            const float* __restrict__ C_syn_i,
                            const float* __restrict__ Tau_syn,
                            const float* __restrict__ Delta_syn,
                            const float* __restrict__ W_syn,
                            const float* __restrict__ Tau_spk,
                            const float* __restrict__ W_spk,
                            const float* __restrict__ W_hist,
                            float* __restrict__ filt_out)
{
    int tid = threadIdx.x;
    int nt  = blockDim.x;

    for (int e = tid; e < E_NOC; e += nt) {
        int k = 0;
        for (int s = 0; s < SUBN; s++)
            if (C_syn_e[s * E_NOC + e] > 0.5f) k = s;
        g_idx_e[e] = k;
    }
    for (int e = tid; e < I_NOC; e += nt) {
        int k = 0;
        for (int s = 0; s < SUBN; s++)
            if (C_syn_i[s * I_NOC + e] > 0.5f) k = s;
        g_idx_i[e] = k;
    }

    const float PIF = 3.14159265358979323846f;
    for (int i = tid; i < SUBN * T_NO; i += nt) {
        int s = i / T_NO;
        int m = i % T_NO;
        float mf = (float)m;

        float te  = fmaxf(mf - expf(Delta_syn[s * 2 + 0]), 0.0f);
        float tte = te / expf(Tau_syn[s * 2 + 0]);
        float ek  = tte * expf(-tte) * expf(W_syn[s * 2 + 0]);

        float td  = fmaxf(mf - expf(Delta_syn[s * 2 + 1]), 0.0f);
        float tti = td / expf(Tau_syn[s * 2 + 1]);
        float ik  = -tti * expf(-tti) * expf(W_syn[s * 2 + 1]);

        float tts = mf / expf(Tau_spk[s]);
        float sk  = tts * expf(-tts) * expf(W_spk[s]);

        float raw = 4.0f * logf(mf + 1.0f);
        float hk  = 0.0f;
        for (int c = 0; c < COS_NO; c++) {
            float phi = (PIF * 0.5f) * (float)c;
            if (raw >= phi - PIF && raw <= phi + PIF)
                hk += W_hist[s * COS_NO + c] * (0.5f * cosf(raw - phi) + 0.5f);
        }

        g_ek[i]    = ek;
        g_ik[i]    = ik;
        g_spkk[i]  = sk;
        g_histk[i] = hk;

        filt_out[(0 * SUBN + s) * T_NO + m] = ek;
        filt_out[(1 * SUBN + s) * T_NO + m] = ik;
        filt_out[(2 * SUBN + s) * T_NO + m] = sk;
        filt_out[(3 * SUBN + s) * T_NO + m] = hk;
    }
    __syncthreads();

    // nibble LUT: lutn[s][i][n] = sum_j bit_j(n) * histk[s][4i+j]
    for (int i = tid; i < SUBN * 800; i += nt) {
        int s = i / 800;
        int r = i % 800;
        int k = r >> 4;
        int n = r & 15;
        float v = 0.0f;
        for (int j = 0; j < 4; j++) {
            int m = 4 * k + j;
            if (m < T_NO && ((n >> j) & 1)) v += g_histk[s * T_NO + m];
        }
        g_lutn[i] = v;
    }
}

// ---------------- K1: one-hot scatter-sum ----------------
__global__ void agg_kernel(const float* __restrict__ S_e,
                           const float* __restrict__ S_i)
{
    __shared__ float acc_e[SUBN];
    __shared__ float acc_i[SUBN];
    int t   = blockIdx.x;
    int tid = threadIdx.x;
    if (tid < SUBN) { acc_e[tid] = 0.0f; acc_i[tid] = 0.0f; }
    __syncthreads();

    const float* re = S_e + (size_t)t * E_NOC;
    for (int e = tid; e < E_NOC; e += blockDim.x) {
        float v = re[e];
        if (v != 0.0f) atomicAdd(&acc_e[g_idx_e[e]], v);
    }
    const float* ri = S_i + (size_t)t * I_NOC;
    for (int e = tid; e < I_NOC; e += blockDim.x) {
        float v = ri[e];
        if (v != 0.0f) atomicAdd(&acc_i[g_idx_i[e]], v);
    }
    __syncthreads();
    if (tid < SUBN) {
        g_se[t * SUBN + tid] = acc_e[tid];
        g_si[t * SUBN + tid] = acc_i[tid];
    }
}

// ---------------- K2: causal FIR, smem-staged, Theta folded in ----------------
#define CONV_TS 256
#define CONV_THREADS 512
#define CONV_ROWS (CONV_TS + T_NO)
#define CONV_SMEM_FLOATS (4000 + 4000 + CONV_ROWS*SUBN + CONV_ROWS*SUBN)

__global__ void __launch_bounds__(CONV_THREADS, 1)
conv_kernel(const float* __restrict__ Theta)
{
    extern __shared__ float cs[];
    float* ek   = cs;
    float* ik   = ek + 4000;
    float* se_s = ik + 4000;
    float* si_s = se_s + CONV_ROWS * SUBN;

    int tid = threadIdx.x;
    int t0  = blockIdx.x * CONV_TS;

    for (int i = tid; i < SUBN * T_NO; i += CONV_THREADS) {
        ek[i] = g_ek[i];
        ik[i] = g_ik[i];
    }
    for (int i = tid; i < CONV_ROWS * SUBN; i += CONV_THREADS) {
        int r  = i / SUBN;
        int s  = i % SUBN;
        int tg = t0 - T_NO + r;
        float ve = 0.0f, vi = 0.0f;
        if (tg >= 0 && tg < T_DATA) {
            ve = g_se[tg * SUBN + s];
            vi = g_si[tg * SUBN + s];
        }
        se_s[i] = ve;
        si_s[i] = vi;
    }
    __syncthreads();

    for (int wi = tid; wi < CONV_TS * SUBN; wi += CONV_THREADS) {
        int tt = t0 + wi / SUBN;
        int s  = wi % SUBN;
        if (tt >= T_DATA) continue;
        int mmax = min(T_NO, tt);
        int base = ((tt - t0 + T_NO - 1) * SUBN) + s;
        const float* eks = ek + s * T_NO;
        const float* iks = ik + s * T_NO;
        float a0 = 0.0f, a1 = 0.0f;
        for (int m = 0; m < mmax; m++) {
            int ai = base - m * SUBN;
            a0 = fmaf(eks[m], se_s[ai], a0);
            a1 = fmaf(iks[m], si_s[ai], a1);
        }
        g_syn[tt * SUBN + s] = a0 + a1 + Theta[s];
    }
}

// ---------------- K3: blocked recurrence, spike-bitstream + nibble LUTs ----------
// Spike history lives as 32-bit words: bit j of bword[s][blk] = z[s][32*blk+31-j]
// (= leader's zmask at end of block blk). All hist taps are nibble lookups.
#define RECUR_THREADS 448               // 14 warps; warp 13 = leader
#define EPITCH 21
#define BWPITCH 17

#define OFF_LUTN 0                                    // [20][50][16] = 16000
#define OFF_ETOT (OFF_LUTN + SUBN*800)                // [32][21]
#define OFF_HFAR (OFF_ETOT + BW*EPITCH)               // [32][21]
#define OFF_SYNB (OFF_HFAR + BW*EPITCH)               // [32][21]
#define OFF_BWR  (OFF_SYNB + BW*EPITCH)               // [20][17] u32 ring (16 blocks)
#define RECUR_SMEM_FLOATS (OFF_BWR + SUBN*BWPITCH)

__global__ void __launch_bounds__(RECUR_THREADS, 1)
recur_kernel(const float* __restrict__ C_den,
             const float* __restrict__ Tau_spk,
             const float* __restrict__ W_spk)
{
    extern __shared__ float sm[];
    float*    lutn = sm + OFF_LUTN;
    float*    Etot = sm + OFF_ETOT;
    float*    Hfar = sm + OFF_HFAR;
    float*    synb = sm + OFF_SYNB;
    unsigned* bwr  = (unsigned*)(sm + OFF_BWR);

    int tid  = threadIdx.x;
    int w    = tid >> 5;
    int lane = tid & 31;

    // ---- init smem ----
    for (int i = tid; i < SUBN * 800; i += RECUR_THREADS) lutn[i] = g_lutn[i];
    for (int i = tid; i < BW * EPITCH; i += RECUR_THREADS) {
        int r = i / EPITCH, c = i % EPITCH;
        Hfar[i] = 0.0f;
        Etot[i] = 0.0f;
        synb[i] = (c < SUBN) ? g_syn[r * SUBN + c] : 0.0f;   // block-0 rows
    }
    for (int i = tid; i < SUBN * BWPITCH; i += RECUR_THREADS) bwr[i] = 0u;

    // ---- leader registers ----
    float rr = 0, cc = 0, U = 0, V = 0, qcur = 0, zfprev = 0;
    unsigned zmask = 0;
    float cd[SUBN];
    #pragma unroll
    for (int j = 0; j < SUBN; j++) cd[j] = 0.0f;
    if (w == 13 && lane < SUBN) {
        rr = expf(-expf(-Tau_spk[lane]));
        cc = expf(W_spk[lane] - Tau_spk[lane]);
        #pragma unroll
        for (int j = 0; j < SUBN; j++) cd[j] = C_den[lane * SUBN + j];
    }

    // gather-warp staging row assignment (rows of the NEXT block's syn)
    int r0 = w, r1 = w + 13, r2 = w + 26;   // r2 valid only for w<6
    __syncthreads();

    int p  = lane;                       // output index within block
    bool o = (p == 0);
    unsigned sh = (unsigned)((32 - p) & 31);

    for (int blk = 0; blk < NBLK; blk++) {
        int T0 = blk * BW;

        // ---------- phase A: mid taps m=32..63 (i=8..15) + Etot fold ----------
        if (w < 13) {
            for (int pass = w; pass < SUBN; pass += 13) {
                int s = pass;
                const unsigned* bb = &bwr[s * BWPITCH];
                unsigned v0 = bb[(blk - 1) & 15];
                unsigned v1 = bb[(blk - 2) & 15];
                unsigned v2 = bb[(blk - 3) & 15];
                unsigned w0 = o ? v1 : v0;
                unsigned w1 = o ? v2 : v1;
                unsigned a0 = __funnelshift_r(w0, w1, sh);  // 8 nibbles = 32 bits
                const float* lp = &lutn[s * 800 + 8 * 16];
                float h0 = lp[0  + (a0 & 15u)]
                         + lp[16 + ((a0 >> 4) & 15u)];
                float h1 = lp[32 + ((a0 >> 8) & 15u)]
                         + lp[48 + ((a0 >> 12) & 15u)];
                float h2 = lp[64 + ((a0 >> 16) & 15u)]
                         + lp[80 + ((a0 >> 20) & 15u)];
                float h3 = lp[96 + ((a0 >> 24) & 15u)]
                         + lp[112 + (a0 >> 28)];
                int oo = p * EPITCH + s;
                Etot[oo] = ((h0 + h1) + (h2 + h3)) + Hfar[oo] + synb[oo];
            }
        }
        __syncthreads();

        // ---------- phase B ----------
        if (w == 13) {
            // leader: 32 sequential steps, barrier-free; near taps m=0..31 from zmask
            for (int pp = 0; pp < BW; pp++) {
                int t = T0 + pp;
                float sv = 0.0f;
                if (lane < SUBN) {
                    U = fmaf(rr, U, zfprev);      // u[t] from z[t-1]
                    V = rr * (V + U);             // v[t+1]
                    const float* lp = &lutn[lane * 800];
                    float l0 = lp[0   + (zmask & 15u)]
                             + lp[16  + ((zmask >> 4) & 15u)];
                    float l1 = lp[32  + ((zmask >> 8) & 15u)]
                             + lp[48  + ((zmask >> 12) & 15u)];
                    float l2 = lp[64  + ((zmask >> 16) & 15u)]
                             + lp[80  + ((zmask >> 20) & 15u)];
                    float l3 = lp[96  + ((zmask >> 24) & 15u)]
                             + lp[112 + (zmask >> 28)];
                    sv = Etot[pp * EPITCH + lane] + ((l0 + l1) + (l2 + l3));
                }
                // C_den @ q via 4 independent shfl+FMA chains
                float a0 = 0, a1 = 0, a2 = 0, a3 = 0;
                #pragma unroll
                for (int j = 0; j < 5; j++) {
                    float q0 = __shfl_sync(0xFFFFFFFFu, qcur, j);
                    float q1 = __shfl_sync(0xFFFFFFFFu, qcur, j + 5);
                    float q2 = __shfl_sync(0xFFFFFFFFu, qcur, j + 10);
                    float q3 = __shfl_sync(0xFFFFFFFFu, qcur, j + 15);
                    a0 = fmaf(cd[j],      q0, a0);
                    a1 = fmaf(cd[j + 5],  q1, a1);
                    a2 = fmaf(cd[j + 10], q2, a2);
                    a3 = fmaf(cd[j + 15], q3, a3);
                }
                if (lane < SUBN) {
                    sv += (a0 + a1) + (a2 + a3);
                    float zf = (sv > 0.0f) ? 1.0f : 0.0f;
                    if (t < T_DATA) g_sv[t * SUBN + lane] = sv;
                    zmask  = (zmask << 1) | (sv > 0.0f ? 1u : 0u);
                    zfprev = zf;
                    qcur   = cc * V;              // q[t+1]
                }
            }
            // publish this block's spike word
            if (lane < SUBN) bwr[lane * BWPITCH + (blk & 15)] = zmask;
        } else {
            // prefetch next-block syn rows into registers (MLP-hidden)
            float pf0 = 0.0f, pf1 = 0.0f, pf2 = 0.0f;
            if (lane < SUBN) {
                int tg0 = T0 + BW + r0;
                int tg1 = T0 + BW + r1;
                pf0 = (tg0 < T_DATA) ? g_syn[tg0 * SUBN + lane] : 0.0f;
                pf1 = (tg1 < T_DATA) ? g_syn[tg1 * SUBN + lane] : 0.0f;
                if (r2 < BW) {
                    int tg2 = T0 + BW + r2;
                    pf2 = (tg2 < T_DATA) ? g_syn[tg2 * SUBN + lane] : 0.0f;
                }
            }

            // far taps m=64..199 (i=16..49) for NEXT block; uses words <= blk-1
            for (int pass = w; pass < SUBN; pass += 13) {
                int s = pass;
                const unsigned* bb = &bwr[s * BWPITCH];
                unsigned v0 = bb[(blk - 1) & 15];
                unsigned v1 = bb[(blk - 2) & 15];
                unsigned v2 = bb[(blk - 3) & 15];
                unsigned v3 = bb[(blk - 4) & 15];
                unsigned v4 = bb[(blk - 5) & 15];
                unsigned v5 = bb[(blk - 6) & 15];
                unsigned v6 = bb[(blk - 7) & 15];
                unsigned w0 = o ? v1 : v0;
                unsigned w1 = o ? v2 : v1;
                unsigned w2 = o ? v3 : v2;
                unsigned w3 = o ? v4 : v3;
                unsigned w4 = o ? v5 : v4;
                unsigned w5 = o ? v6 : v5;
                unsigned aw0 = __funnelshift_r(w0, w1, sh);
                unsigned aw1 = __funnelshift_r(w1, w2, sh);
                unsigned aw2 = __funnelshift_r(w2, w3, sh);
                unsigned aw3 = __funnelshift_r(w3, w4, sh);
                unsigned aw4 = __funnelshift_r(w4, w5, sh);
                const float* lp = &lutn[s * 800 + 16 * 16];
                float b0 = 0, b1 = 0, b2 = 0, b3 = 0;
                #pragma unroll
                for (int ii = 0; ii < 34; ii++) {
                    unsigned word = (ii < 8) ? aw0 : (ii < 16) ? aw1 :
                                    (ii < 24) ? aw2 : (ii < 32) ? aw3 : aw4;
                    unsigned nib = (word >> (4 * (ii & 7))) & 15u;
                    float v = lp[ii * 16 + nib];
                    if ((ii & 3) == 0) b0 += v;
                    else if ((ii & 3) == 1) b1 += v;
                    else if ((ii & 3) == 2) b2 += v;
                    else b3 += v;
                }
                Hfar[p * EPITCH + s] = (b0 + b1) + (b2 + b3);
            }

            // store staged rows (phase A of this block already consumed synb)
            if (lane < SUBN) {
                synb[r0 * EPITCH + lane] = pf0;
                synb[r1 * EPITCH + lane] = pf1;
                if (r2 < BW) synb[r2 * EPITCH + lane] = pf2;
            }
        }
        __syncthreads();
    }
}

// ---------------- K4: Z/P from raw pre-activations ----------------
__global__ void zp_kernel(float* __restrict__ Z, float* __restrict__ P)
{
    int idx = blockIdx.x * blockDim.x + threadIdx.x;
    if (idx < T_DATA * SUBN) {
        float sv = g_sv[idx];
        Z[idx] = (sv > 0.0f) ? 1.0f : 0.0f;
        P[idx] = 1.0f / (1.0f + expf(-sv));
    }
}

// ---------------- launch ----------------
extern "C" void kernel_launch(void* const* d_in, const int* in_sizes, int n_in,
                              void* d_out, int out_size)
{
    const float* S_e       = (const float*)d_in[0];
    const float* S_i       = (const float*)d_in[1];
    const float* C_den     = (const float*)d_in[2];
    const float* C_syn_e   = (const float*)d_in[3];
    const float* C_syn_i   = (const float*)d_in[4];
    const float* Tau_syn   = (const float*)d_in[5];
    const float* Delta_syn = (const float*)d_in[6];
    const float* W_syn     = (const float*)d_in[7];
    const float* Tau_spk   = (const float*)d_in[8];
    const float* W_spk     = (const float*)d_in[9];
    const float* W_hist    = (const float*)d_in[10];
    const float* Theta     = (const float*)d_in[11];

    float* out = (float*)d_out;
    float* Z = out;                          // [10000, 20]
    float* P = out + T_DATA * SUBN;          // [10000, 20]
    float* F = out + 2 * T_DATA * SUBN;      // [80, 200]

    prep_kernel<<<1, 256>>>(C_syn_e, C_syn_i, Tau_syn, Delta_syn, W_syn,
                            Tau_spk, W_spk, W_hist, F);
    agg_kernel<<<T_DATA, 256>>>(S_e, S_i);

    cudaFuncSetAttribute(conv_kernel,
                         cudaFuncAttributeMaxDynamicSharedMemorySize,
                         CONV_SMEM_FLOATS * (int)sizeof(float));
    conv_kernel<<<(T_DATA + CONV_TS - 1) / CONV_TS, CONV_THREADS,
                  CONV_SMEM_FLOATS * sizeof(float)>>>(Theta);

    cudaFuncSetAttribute(recur_kernel,
                         cudaFuncAttributeMaxDynamicSharedMemorySize,
                         RECUR_SMEM_FLOATS * (int)sizeof(float));
    recur_kernel<<<1, RECUR_THREADS, RECUR_SMEM_FLOATS * sizeof(float)>>>(
        C_den, Tau_spk, W_spk);

    zp_kernel<<<(T_DATA * SUBN + 255) / 256, 256>>>(Z, P);
}

// round 8
// speedup vs baseline: 1.8875x; 1.8875x over previous
#include <cuda_runtime.h>
#include <math.h>

#define T_NO   200
#define SUBN   20
#define E_NOC  2000
#define I_NOC  500
#define T_DATA 10000
#define COS_NO 17
#define BW     32                       // recurrence block size
#define NBLK   ((T_DATA + BW - 1) / BW) // 313

// ---------------- device scratch (static allocation only) ----------------
__device__ float g_se[T_DATA * SUBN];
__device__ float g_si[T_DATA * SUBN];
__device__ float g_syn[T_DATA * SUBN];    // filtered drive + Theta folded in
__device__ float g_sv[T_DATA * SUBN];     // raw pre-activation
__device__ float g_ek[SUBN * T_NO];
__device__ float g_ik[SUBN * T_NO];
__device__ float g_spkk[SUBN * T_NO];
__device__ float g_histk[SUBN * T_NO];
__device__ float g_lut[SUBN * 1024];      // 4 x 256-entry byte LUTs per subunit (near hist)
__device__ int   g_idx_e[E_NOC];
__device__ int   g_idx_i[I_NOC];

// ---------------- K0: indices + kernels + LUT + filter output ----------------
__global__ void prep_kernel(const float* __restrict__ C_syn_e,
                            const float* __restrict__ C_syn_i,
                            const float* __restrict__ Tau_syn,
                            const float* __restrict__ Delta_syn,
                            const float* __restrict__ W_syn,
                            const float* __restrict__ Tau_spk,
                            const float* __restrict__ W_spk,
                            const float* __restrict__ W_hist,
                            float* __restrict__ filt_out)
{
    int tid = threadIdx.x;
    int nt  = blockDim.x;

    for (int e = tid; e < E_NOC; e += nt) {
        int k = 0;
        for (int s = 0; s < SUBN; s++)
            if (C_syn_e[s * E_NOC + e] > 0.5f) k = s;
        g_idx_e[e] = k;
    }
    for (int e = tid; e < I_NOC; e += nt) {
        int k = 0;
        for (int s = 0; s < SUBN; s++)
            if (C_syn_i[s * I_NOC + e] > 0.5f) k = s;
        g_idx_i[e] = k;
    }

    const float PIF = 3.14159265358979323846f;
    for (int i = tid; i < SUBN * T_NO; i += nt) {
        int s = i / T_NO;
        int m = i % T_NO;
        float mf = (float)m;

        float te  = fmaxf(mf - expf(Delta_syn[s * 2 + 0]), 0.0f);
        float tte = te / expf(Tau_syn[s * 2 + 0]);
        float ek  = tte * expf(-tte) * expf(W_syn[s * 2 + 0]);

        float td  = fmaxf(mf - expf(Delta_syn[s * 2 + 1]), 0.0f);
        float tti = td / expf(Tau_syn[s * 2 + 1]);
        float ik  = -tti * expf(-tti) * expf(W_syn[s * 2 + 1]);

        float tts = mf / expf(Tau_spk[s]);
        float sk  = tts * expf(-tts) * expf(W_spk[s]);

        float raw = 4.0f * logf(mf + 1.0f);
        float hk  = 0.0f;
        for (int c = 0; c < COS_NO; c++) {
            float phi = (PIF * 0.5f) * (float)c;
            if (raw >= phi - PIF && raw <= phi + PIF)
                hk += W_hist[s * COS_NO + c] * (0.5f * cosf(raw - phi) + 0.5f);
        }

        g_ek[i]    = ek;
        g_ik[i]    = ik;
        g_spkk[i]  = sk;
        g_histk[i] = hk;

        filt_out[(0 * SUBN + s) * T_NO + m] = ek;
        filt_out[(1 * SUBN + s) * T_NO + m] = ik;
        filt_out[(2 * SUBN + s) * T_NO + m] = sk;
        filt_out[(3 * SUBN + s) * T_NO + m] = hk;
    }
    __syncthreads();

    // near-hist LUTs: lut[s][k][b] = sum over set bits i of b of histk[s][8k+i]
    for (int i = tid; i < SUBN * 1024; i += nt) {
        int s = i >> 10;
        int k = (i >> 8) & 3;
        int b = i & 255;
        float v = 0.0f;
        for (int j = 0; j < 8; j++)
            if (b & (1 << j)) v += g_histk[s * T_NO + 8 * k + j];
        g_lut[i] = v;
    }
}

// ---------------- K1: one-hot scatter-sum ----------------
__global__ void agg_kernel(const float* __restrict__ S_e,
                           const float* __restrict__ S_i)
{
    __shared__ float acc_e[SUBN];
    __shared__ float acc_i[SUBN];
    int t   = blockIdx.x;
    int tid = threadIdx.x;
    if (tid < SUBN) { acc_e[tid] = 0.0f; acc_i[tid] = 0.0f; }
    __syncthreads();

    const float* re = S_e + (size_t)t * E_NOC;
    for (int e = tid; e < E_NOC; e += blockDim.x) {
        float v = re[e];
        if (v != 0.0f) atomicAdd(&acc_e[g_idx_e[e]], v);
    }
    const float* ri = S_i + (size_t)t * I_NOC;
    for (int e = tid; e < I_NOC; e += blockDim.x) {
        float v = ri[e];
        if (v != 0.0f) atomicAdd(&acc_i[g_idx_i[e]], v);
    }
    __syncthreads();
    if (tid < SUBN) {
        g_se[t * SUBN + tid] = acc_e[tid];
        g_si[t * SUBN + tid] = acc_i[tid];
    }
}

// ---------------- K2: causal FIR, smem-staged, Theta folded in ----------------
#define CONV_TS 256
#define CONV_THREADS 512
#define CONV_ROWS (CONV_TS + T_NO)
#define CONV_SMEM_FLOATS (4000 + 4000 + CONV_ROWS*SUBN + CONV_ROWS*SUBN)

__global__ void __launch_bounds__(CONV_THREADS, 1)
conv_kernel(const float* __restrict__ Theta)
{
    extern __shared__ float cs[];
    float* ek   = cs;
    float* ik   = ek + 4000;
    float* se_s = ik + 4000;
    float* si_s = se_s + CONV_ROWS * SUBN;

    int tid = threadIdx.x;
    int t0  = blockIdx.x * CONV_TS;

    for (int i = tid; i < SUBN * T_NO; i += CONV_THREADS) {
        ek[i] = g_ek[i];
        ik[i] = g_ik[i];
    }
    for (int i = tid; i < CONV_ROWS * SUBN; i += CONV_THREADS) {
        int r  = i / SUBN;
        int s  = i % SUBN;
        int tg = t0 - T_NO + r;
        float ve = 0.0f, vi = 0.0f;
        if (tg >= 0 && tg < T_DATA) {
            ve = g_se[tg * SUBN + s];
            vi = g_si[tg * SUBN + s];
        }
        se_s[i] = ve;
        si_s[i] = vi;
    }
    __syncthreads();

    for (int wi = tid; wi < CONV_TS * SUBN; wi += CONV_THREADS) {
        int tt = t0 + wi / SUBN;
        int s  = wi % SUBN;
        if (tt >= T_DATA) continue;
        int mmax = min(T_NO, tt);
        int base = ((tt - t0 + T_NO - 1) * SUBN) + s;
        const float* eks = ek + s * T_NO;
        const float* iks = ik + s * T_NO;
        float a0 = 0.0f, a1 = 0.0f;
        for (int m = 0; m < mmax; m++) {
            int ai = base - m * SUBN;
            a0 = fmaf(eks[m], se_s[ai], a0);
            a1 = fmaf(iks[m], si_s[ai], a1);
        }
        g_syn[tt * SUBN + s] = a0 + a1 + Theta[s];
    }
}

// ---------------- K3: blocked recurrence, 14 warps, 2 barriers per 32 steps ----
// Tap split per output t: m=0..31 leader (bitmask + conflict-free LUT),
// m=32..63 phase-A mid, m=64..199 phase-B far gather (one block ahead).
// Leader matvec via broadcast LDS (no SHFL). LUT pitch 1025 (odd) so the 20
// leader lanes land in distinct banks.
#define RECUR_THREADS 448               // 14 warps; warp 13 = leader
#define RPITCH 513                      // doubled ring pitch (conflict-free)
#define EPITCH 21
#define LPITCH 1025                     // LUT pitch per subunit (odd -> no conflicts)

#define OFF_ZRING 0                                   // [20][513]
#define OFF_LUT   (OFF_ZRING + SUBN*RPITCH)           // [20][1025]
#define OFF_KHS   (OFF_LUT + SUBN*LPITCH)             // [20][200]
#define OFF_ETOT  (OFF_KHS + SUBN*T_NO)               // [32][21]
#define OFF_HFAR  (OFF_ETOT + BW*EPITCH)              // [32][21]
#define OFF_SYNB  (OFF_HFAR + BW*EPITCH)              // [32][21]
#define OFF_SHQ   (OFF_SYNB + BW*EPITCH)              // [32]
#define RECUR_SMEM_FLOATS (OFF_SHQ + 32)

__global__ void __launch_bounds__(RECUR_THREADS, 1)
recur_kernel(const float* __restrict__ C_den,
             const float* __restrict__ Tau_spk,
             const float* __restrict__ W_spk)
{
    extern __shared__ float sm[];
    float* zring = sm + OFF_ZRING;
    float* lut   = sm + OFF_LUT;
    float* khs   = sm + OFF_KHS;
    float* Etot  = sm + OFF_ETOT;
    float* Hfar  = sm + OFF_HFAR;
    float* synb  = sm + OFF_SYNB;
    float* shq   = sm + OFF_SHQ;

    int tid  = threadIdx.x;
    int w    = tid >> 5;
    int lane = tid & 31;

    // ---- init smem ----
    for (int i = tid; i < SUBN * RPITCH; i += RECUR_THREADS) zring[i] = 0.0f;
    for (int i = tid; i < SUBN * 1024; i += RECUR_THREADS)
        lut[(i >> 10) * LPITCH + (i & 1023)] = g_lut[i];
    for (int i = tid; i < SUBN * T_NO; i += RECUR_THREADS) khs[i] = g_histk[i];
    for (int i = tid; i < BW * EPITCH; i += RECUR_THREADS) {
        int r = i / EPITCH, c = i % EPITCH;
        Hfar[i] = 0.0f;
        Etot[i] = 0.0f;
        synb[i] = (c < SUBN) ? g_syn[r * SUBN + c] : 0.0f;   // block-0 rows
    }
    if (tid < 32) shq[tid] = 0.0f;

    // ---- leader registers ----
    float rr = 0, cc = 0, U = 0, V = 0, zfprev = 0;
    unsigned zmask = 0;
    float cd[SUBN];
    #pragma unroll
    for (int j = 0; j < SUBN; j++) cd[j] = 0.0f;
    if (w == 13 && lane < SUBN) {
        rr = expf(-expf(-Tau_spk[lane]));
        cc = expf(W_spk[lane] - Tau_spk[lane]);
        #pragma unroll
        for (int j = 0; j < SUBN; j++) cd[j] = C_den[lane * SUBN + j];
    }

    // gather-warp staging row assignment (rows of the NEXT block's syn)
    int r0 = w, r1 = w + 13, r2 = w + 26;   // r2 valid only for w<6
    __syncthreads();

    for (int blk = 0; blk < NBLK; blk++) {
        int T0 = blk * BW;

        // ---------- phase A: mid taps (m=32..63) + Etot fold (warps 0..12) ----------
        if (w < 13) {
            for (int pass = w; pass < SUBN; pass += 13) {
                int s = pass;
                const float*  zp0 = &zring[s * RPITCH + 256 + ((T0 + lane - 1) & 255)];
                const float4* k4p = (const float4*)&khs[s * T_NO];
                float a0 = 0, a1 = 0, a2 = 0, a3 = 0;
                #pragma unroll
                for (int g = 8; g < 16; g++) {            // m = 32..63
                    float4 k4 = k4p[g];
                    a0 = fmaf(k4.x, zp0[-(4 * g + 0)], a0);
                    a1 = fmaf(k4.y, zp0[-(4 * g + 1)], a1);
                    a2 = fmaf(k4.z, zp0[-(4 * g + 2)], a2);
                    a3 = fmaf(k4.w, zp0[-(4 * g + 3)], a3);
                }
                int o = lane * EPITCH + s;
                Etot[o] = ((a0 + a1) + (a2 + a3)) + Hfar[o] + synb[o];
            }
        }
        __syncthreads();

        // ---------- phase B ----------
        if (w == 13) {
            // leader: 32 sequential steps, barrier-free
            for (int p = 0; p < BW; p++) {
                int t = T0 + p;
                // C_den @ q[t] via broadcast LDS of shq (stored last step) + 4 FMA chains
                const float4* qv = (const float4*)shq;
                float4 q0 = qv[0], q1 = qv[1], q2 = qv[2], q3 = qv[3], q4 = qv[4];
                float a0 = 0, a1 = 0, a2 = 0, a3 = 0;
                a0 = fmaf(cd[0],  q0.x, a0); a1 = fmaf(cd[1],  q0.y, a1);
                a2 = fmaf(cd[2],  q0.z, a2); a3 = fmaf(cd[3],  q0.w, a3);
                a0 = fmaf(cd[4],  q1.x, a0); a1 = fmaf(cd[5],  q1.y, a1);
                a2 = fmaf(cd[6],  q1.z, a2); a3 = fmaf(cd[7],  q1.w, a3);
                a0 = fmaf(cd[8],  q2.x, a0); a1 = fmaf(cd[9],  q2.y, a1);
                a2 = fmaf(cd[10], q2.z, a2); a3 = fmaf(cd[11], q2.w, a3);
                a0 = fmaf(cd[12], q3.x, a0); a1 = fmaf(cd[13], q3.y, a1);
                a2 = fmaf(cd[14], q3.z, a2); a3 = fmaf(cd[15], q3.w, a3);
                a0 = fmaf(cd[16], q4.x, a0); a1 = fmaf(cd[17], q4.y, a1);
                a2 = fmaf(cd[18], q4.z, a2); a3 = fmaf(cd[19], q4.w, a3);

                if (lane < SUBN) {
                    U = fmaf(rr, U, zfprev);      // u[t] from z[t-1]
                    V = rr * (V + U);             // v[t+1]
                    const float* lp = &lut[lane * LPITCH];
                    float sv = Etot[p * EPITCH + lane];
                    sv += lp[        (zmask & 255u)];
                    sv += lp[256 + ((zmask >> 8)  & 255u)];
                    sv += lp[512 + ((zmask >> 16) & 255u)];
                    sv += lp[768 +  (zmask >> 24)];
                    sv += (a0 + a1) + (a2 + a3);
                    float zf = (sv > 0.0f) ? 1.0f : 0.0f;
                    int slot = t & 255;
                    zring[lane * RPITCH + slot]       = zf;
                    zring[lane * RPITCH + slot + 256] = zf;
                    if (t < T_DATA) g_sv[t * SUBN + lane] = sv;
                    zmask  = (zmask << 1) | (sv > 0.0f ? 1u : 0u);
                    zfprev = zf;
                    shq[lane] = cc * V;           // publish q[t+1]
                }
                __syncwarp();
            }
        } else {
            // prefetch next-block syn rows into registers (MLP-hidden)
            float pf0 = 0.0f, pf1 = 0.0f, pf2 = 0.0f;
            if (lane < SUBN) {
                int tg0 = T0 + BW + r0;
                int tg1 = T0 + BW + r1;
                pf0 = (tg0 < T_DATA) ? g_syn[tg0 * SUBN + lane] : 0.0f;
                pf1 = (tg1 < T_DATA) ? g_syn[tg1 * SUBN + lane] : 0.0f;
                if (r2 < BW) {
                    int tg2 = T0 + BW + r2;
                    pf2 = (tg2 < T_DATA) ? g_syn[tg2 * SUBN + lane] : 0.0f;
                }
            }

            // far gather for NEXT block: m = 64..199 (reads z <= T0-2 only)
            int T0n = T0 + BW;
            for (int pass = w; pass < SUBN; pass += 13) {
                int s = pass;
                const float*  zp0 = &zring[s * RPITCH + 256 + ((T0n + lane - 1) & 255)];
                const float4* k4p = (const float4*)&khs[s * T_NO];
                float a0 = 0, a1 = 0, a2 = 0, a3 = 0;
                #pragma unroll
                for (int g = 16; g < 50; g++) {           // m = 64..199
                    float4 k4 = k4p[g];
                    a0 = fmaf(k4.x, zp0[-(4 * g + 0)], a0);
                    a1 = fmaf(k4.y, zp0[-(4 * g + 1)], a1);
                    a2 = fmaf(k4.z, zp0[-(4 * g + 2)], a2);
                    a3 = fmaf(k4.w, zp0[-(4 * g + 3)], a3);
                }
                Hfar[lane * EPITCH + s] = (a0 + a1) + (a2 + a3);
            }

            // store staged rows (phase A of this block already consumed synb)
            if (lane < SUBN) {
                synb[r0 * EPITCH + lane] = pf0;
                synb[r1 * EPITCH + lane] = pf1;
                if (r2 < BW) synb[r2 * EPITCH + lane] = pf2;
            }
        }
        __syncthreads();
    }
}

// ---------------- K4: Z/P from raw pre-activations ----------------
__global__ void zp_kernel(float* __restrict__ Z, float* __restrict__ P)
{
    int idx = blockIdx.x * blockDim.x + threadIdx.x;
    if (idx < T_DATA * SUBN) {
        float sv = g_sv[idx];
        Z[idx] = (sv > 0.0f) ? 1.0f : 0.0f;
        P[idx] = 1.0f / (1.0f + expf(-sv));
    }
}

// ---------------- launch ----------------
extern "C" void kernel_launch(void* const* d_in, const int* in_sizes, int n_in,
                              void* d_out, int out_size)
{
    const float* S_e       = (const float*)d_in[0];
    const float* S_i       = (const float*)d_in[1];
    const float* C_den     = (const float*)d_in[2];
    const float* C_syn_e   = (const float*)d_in[3];
    const float* C_syn_i   = (const float*)d_in[4];
    const float* Tau_syn   = (const float*)d_in[5];
    const float* Delta_syn = (const float*)d_in[6];
    const float* W_syn     = (const float*)d_in[7];
    const float* Tau_spk   = (const float*)d_in[8];
    const float* W_spk     = (const float*)d_in[9];
    const float* W_hist    = (const float*)d_in[10];
    const float* Theta     = (const float*)d_in[11];

    float* out = (float*)d_out;
    float* Z = out;                          // [10000, 20]
    float* P = out + T_DATA * SUBN;          // [10000, 20]
    float* F = out + 2 * T_DATA * SUBN;      // [80, 200]

    prep_kernel<<<1, 256>>>(C_syn_e, C_syn_i, Tau_syn, Delta_syn, W_syn,
                            Tau_spk, W_spk, W_hist, F);
    agg_kernel<<<T_DATA, 256>>>(S_e, S_i);

    cudaFuncSetAttribute(conv_kernel,
                         cudaFuncAttributeMaxDynamicSharedMemorySize,
                         CONV_SMEM_FLOATS * (int)sizeof(float));
    conv_kernel<<<(T_DATA + CONV_TS - 1) / CONV_TS, CONV_THREADS,
                  CONV_SMEM_FLOATS * sizeof(float)>>>(Theta);

    cudaFuncSetAttribute(recur_kernel,
                         cudaFuncAttributeMaxDynamicSharedMemorySize,
                         RECUR_SMEM_FLOATS * (int)sizeof(float));
    recur_kernel<<<1, RECUR_THREADS, RECUR_SMEM_FLOATS * sizeof(float)>>>(
        C_den, Tau_spk, W_spk);

    zp_kernel<<<(T_DATA * SUBN + 255) / 256, 256>>>(Z, P);
}

// round 9
// speedup vs baseline: 2.2597x; 1.1972x over previous
#include <cuda_runtime.h>
#include <math.h>

#define T_NO   200
#define SUBN   20
#define E_NOC  2000
#define I_NOC  500
#define T_DATA 10000
#define COS_NO 17
#define BW     32                       // recurrence block size
#define NBLK   ((T_DATA + BW - 1) / BW) // 313

// ---------------- device scratch (static allocation only) ----------------
__device__ float g_se[T_DATA * SUBN];
__device__ float g_si[T_DATA * SUBN];
__device__ float g_syn[T_DATA * SUBN];    // filtered drive + Theta folded in
__device__ float g_sv[T_DATA * SUBN];     // raw pre-activation
__device__ float g_ek[SUBN * T_NO];
__device__ float g_ik[SUBN * T_NO];
__device__ float g_spkk[SUBN * T_NO];
__device__ float g_histk[SUBN * T_NO];
__device__ float g_lut[SUBN * 1024];      // byte LUT (leader, near taps m=0..31)
__device__ float g_lutn[SUBN * 800];      // nibble LUT (gathers): [s][i=0..49][n=0..15]
__device__ int   g_idx_e[E_NOC];
__device__ int   g_idx_i[I_NOC];

// ---------------- K0: indices + kernels + LUTs + filter output ----------------
__global__ void prep_kernel(const float* __restrict__ C_syn_e,
                            const float* __restrict__ C_syn_i,
                            const float* __restrict__ Tau_syn,
                            const float* __restrict__ Delta_syn,
                            const float* __restrict__ W_syn,
                            const float* __restrict__ Tau_spk,
                            const float* __restrict__ W_spk,
                            const float* __restrict__ W_hist,
                            float* __restrict__ filt_out)
{
    int tid = threadIdx.x;
    int nt  = blockDim.x;

    for (int e = tid; e < E_NOC; e += nt) {
        int k = 0;
        for (int s = 0; s < SUBN; s++)
            if (C_syn_e[s * E_NOC + e] > 0.5f) k = s;
        g_idx_e[e] = k;
    }
    for (int e = tid; e < I_NOC; e += nt) {
        int k = 0;
        for (int s = 0; s < SUBN; s++)
            if (C_syn_i[s * I_NOC + e] > 0.5f) k = s;
        g_idx_i[e] = k;
    }

    const float PIF = 3.14159265358979323846f;
    for (int i = tid; i < SUBN * T_NO; i += nt) {
        int s = i / T_NO;
        int m = i % T_NO;
        float mf = (float)m;

        float te  = fmaxf(mf - expf(Delta_syn[s * 2 + 0]), 0.0f);
        float tte = te / expf(Tau_syn[s * 2 + 0]);
        float ek  = tte * expf(-tte) * expf(W_syn[s * 2 + 0]);

        float td  = fmaxf(mf - expf(Delta_syn[s * 2 + 1]), 0.0f);
        float tti = td / expf(Tau_syn[s * 2 + 1]);
        float ik  = -tti * expf(-tti) * expf(W_syn[s * 2 + 1]);

        float tts = mf / expf(Tau_spk[s]);
        float sk  = tts * expf(-tts) * expf(W_spk[s]);

        float raw = 4.0f * logf(mf + 1.0f);
        float hk  = 0.0f;
        for (int c = 0; c < COS_NO; c++) {
            float phi = (PIF * 0.5f) * (float)c;
            if (raw >= phi - PIF && raw <= phi + PIF)
                hk += W_hist[s * COS_NO + c] * (0.5f * cosf(raw - phi) + 0.5f);
        }

        g_ek[i]    = ek;
        g_ik[i]    = ik;
        g_spkk[i]  = sk;
        g_histk[i] = hk;

        filt_out[(0 * SUBN + s) * T_NO + m] = ek;
        filt_out[(1 * SUBN + s) * T_NO + m] = ik;
        filt_out[(2 * SUBN + s) * T_NO + m] = sk;
        filt_out[(3 * SUBN + s) * T_NO + m] = hk;
    }
    __syncthreads();

    // byte LUT: lut[s][k][b] = sum over set bits i of b of histk[s][8k+i]
    for (int i = tid; i < SUBN * 1024; i += nt) {
        int s = i >> 10;
        int k = (i >> 8) & 3;
        int b = i & 255;
        float v = 0.0f;
        for (int j = 0; j < 8; j++)
            if (b & (1 << j)) v += g_histk[s * T_NO + 8 * k + j];
        g_lut[i] = v;
    }
    // nibble LUT: lutn[s][i][n] = sum_j bit_j(n) * histk[s][4i+j]
    for (int i = tid; i < SUBN * 800; i += nt) {
        int s = i / 800;
        int r = i % 800;
        int k = r >> 4;
        int n = r & 15;
        float v = 0.0f;
        for (int j = 0; j < 4; j++) {
            int m = 4 * k + j;
            if (m < T_NO && ((n >> j) & 1)) v += g_histk[s * T_NO + m];
        }
        g_lutn[i] = v;
    }
}

// ---------------- K1: one-hot scatter-sum ----------------
__global__ void agg_kernel(const float* __restrict__ S_e,
                           const float* __restrict__ S_i)
{
    __shared__ float acc_e[SUBN];
    __shared__ float acc_i[SUBN];
    int t   = blockIdx.x;
    int tid = threadIdx.x;
    if (tid < SUBN) { acc_e[tid] = 0.0f; acc_i[tid] = 0.0f; }
    __syncthreads();

    const float* re = S_e + (size_t)t * E_NOC;
    for (int e = tid; e < E_NOC; e += blockDim.x) {
        float v = re[e];
        if (v != 0.0f) atomicAdd(&acc_e[g_idx_e[e]], v);
    }
    const float* ri = S_i + (size_t)t * I_NOC;
    for (int e = tid; e < I_NOC; e += blockDim.x) {
        float v = ri[e];
        if (v != 0.0f) atomicAdd(&acc_i[g_idx_i[e]], v);
    }
    __syncthreads();
    if (tid < SUBN) {
        g_se[t * SUBN + tid] = acc_e[tid];
        g_si[t * SUBN + tid] = acc_i[tid];
    }
}

// ---------------- K2: causal FIR, smem-staged, Theta folded in ----------------
#define CONV_TS 256
#define CONV_THREADS 512
#define CONV_ROWS (CONV_TS + T_NO)
#define CONV_SMEM_FLOATS (4000 + 4000 + CONV_ROWS*SUBN + CONV_ROWS*SUBN)

__global__ void __launch_bounds__(CONV_THREADS, 1)
conv_kernel(const float* __restrict__ Theta)
{
    extern __shared__ float cs[];
    float* ek   = cs;
    float* ik   = ek + 4000;
    float* se_s = ik + 4000;
    float* si_s = se_s + CONV_ROWS * SUBN;

    int tid = threadIdx.x;
    int t0  = blockIdx.x * CONV_TS;

    for (int i = tid; i < SUBN * T_NO; i += CONV_THREADS) {
        ek[i] = g_ek[i];
        ik[i] = g_ik[i];
    }
    for (int i = tid; i < CONV_ROWS * SUBN; i += CONV_THREADS) {
        int r  = i / SUBN;
        int s  = i % SUBN;
        int tg = t0 - T_NO + r;
        float ve = 0.0f, vi = 0.0f;
        if (tg >= 0 && tg < T_DATA) {
            ve = g_se[tg * SUBN + s];
            vi = g_si[tg * SUBN + s];
        }
        se_s[i] = ve;
        si_s[i] = vi;
    }
    __syncthreads();

    for (int wi = tid; wi < CONV_TS * SUBN; wi += CONV_THREADS) {
        int tt = t0 + wi / SUBN;
        int s  = wi % SUBN;
        if (tt >= T_DATA) continue;
        int mmax = min(T_NO, tt);
        int base = ((tt - t0 + T_NO - 1) * SUBN) + s;
        const float* eks = ek + s * T_NO;
        const float* iks = ik + s * T_NO;
        float a0 = 0.0f, a1 = 0.0f;
        for (int m = 0; m < mmax; m++) {
            int ai = base - m * SUBN;
            a0 = fmaf(eks[m], se_s[ai], a0);
            a1 = fmaf(iks[m], si_s[ai], a1);
        }
        g_syn[tt * SUBN + s] = a0 + a1 + Theta[s];
    }
}

// ---------------- K3: blocked recurrence, bitstream history ----------------
// Spike history = 32-bit words (bit k of word blk = z[32*blk+31-k]).
// Leader: near taps m=0..31 via conflict-free byte LUT (pitch 1025),
//         matvec via broadcast LDS, exact spk recurrence.
// Gathers: mid (m=32..63, phase A) and far (m=64..199, phase B, one block
//          ahead) via funnel-shifted bitstream + nibble LUT (pitch 801).
#define RECUR_THREADS 448               // 14 warps; warp 13 = leader
#define EPITCH 21
#define LPITCH 1025                     // byte LUT pitch (odd)
#define NPITCH 801                      // nibble LUT pitch (odd)
#define BWPITCH 17

#define OFF_LUT   0                                   // [20][1025]
#define OFF_LUTN  (OFF_LUT + SUBN*LPITCH)             // [20][801]
#define OFF_ETOT  (OFF_LUTN + SUBN*NPITCH)            // [32][21]
#define OFF_HFAR  (OFF_ETOT + BW*EPITCH)              // [32][21]
#define OFF_SYNB  (OFF_HFAR + BW*EPITCH)              // [32][21]
#define OFF_SHQ   (OFF_SYNB + BW*EPITCH)              // [32]
#define OFF_BWR   (OFF_SHQ + 32)                      // [20][17] u32 ring
#define RECUR_SMEM_FLOATS (OFF_BWR + SUBN*BWPITCH)

__global__ void __launch_bounds__(RECUR_THREADS, 1)
recur_kernel(const float* __restrict__ C_den,
             const float* __restrict__ Tau_spk,
             const float* __restrict__ W_spk)
{
    extern __shared__ float sm[];
    float*    lut  = sm + OFF_LUT;
    float*    lutn = sm + OFF_LUTN;
    float*    Etot = sm + OFF_ETOT;
    float*    Hfar = sm + OFF_HFAR;
    float*    synb = sm + OFF_SYNB;
    float*    shq  = sm + OFF_SHQ;
    unsigned* bwr  = (unsigned*)(sm + OFF_BWR);

    int tid  = threadIdx.x;
    int w    = tid >> 5;
    int lane = tid & 31;

    // ---- init smem ----
    for (int i = tid; i < SUBN * 1024; i += RECUR_THREADS)
        lut[(i >> 10) * LPITCH + (i & 1023)] = g_lut[i];
    for (int i = tid; i < SUBN * 800; i += RECUR_THREADS)
        lutn[(i / 800) * NPITCH + (i % 800)] = g_lutn[i];
    for (int i = tid; i < BW * EPITCH; i += RECUR_THREADS) {
        int r = i / EPITCH, c = i % EPITCH;
        Hfar[i] = 0.0f;
        Etot[i] = 0.0f;
        synb[i] = (c < SUBN) ? g_syn[r * SUBN + c] : 0.0f;   // block-0 rows
    }
    for (int i = tid; i < SUBN * BWPITCH; i += RECUR_THREADS) bwr[i] = 0u;
    if (tid < 32) shq[tid] = 0.0f;

    // ---- leader registers ----
    float rr = 0, cc = 0, U = 0, V = 0, zfprev = 0;
    unsigned zmask = 0;
    float cd[SUBN];
    #pragma unroll
    for (int j = 0; j < SUBN; j++) cd[j] = 0.0f;
    if (w == 13 && lane < SUBN) {
        rr = expf(-expf(-Tau_spk[lane]));
        cc = expf(W_spk[lane] - Tau_spk[lane]);
        #pragma unroll
        for (int j = 0; j < SUBN; j++) cd[j] = C_den[lane * SUBN + j];
    }

    // gather-warp staging row assignment (rows of the NEXT block's syn)
    int r0 = w, r1 = w + 13, r2 = w + 26;   // r2 valid only for w<6
    __syncthreads();

    int p  = lane;                       // output index within block
    bool o = (p == 0);
    unsigned sh = (unsigned)((32 - p) & 31);

    for (int blk = 0; blk < NBLK; blk++) {
        int T0 = blk * BW;

        // ---------- phase A: mid taps m=32..63 (i=8..15) + Etot fold ----------
        if (w < 13) {
            for (int pass = w; pass < SUBN; pass += 13) {
                int s = pass;
                const unsigned* bb = &bwr[s * BWPITCH];
                unsigned v0 = bb[(blk - 1) & 15];
                unsigned v1 = bb[(blk - 2) & 15];
                unsigned v2 = bb[(blk - 3) & 15];
                unsigned w0 = o ? v1 : v0;
                unsigned w1 = o ? v2 : v1;
                unsigned a0 = __funnelshift_r(w0, w1, sh);  // 8 nibbles = 32 bits
                const float* lp = &lutn[s * NPITCH + 8 * 16];
                float h0 = lp[0  + (a0 & 15u)]
                         + lp[16 + ((a0 >> 4) & 15u)];
                float h1 = lp[32 + ((a0 >> 8) & 15u)]
                         + lp[48 + ((a0 >> 12) & 15u)];
                float h2 = lp[64 + ((a0 >> 16) & 15u)]
                         + lp[80 + ((a0 >> 20) & 15u)];
                float h3 = lp[96 + ((a0 >> 24) & 15u)]
                         + lp[112 + (a0 >> 28)];
                int oo = p * EPITCH + s;
                Etot[oo] = ((h0 + h1) + (h2 + h3)) + Hfar[oo] + synb[oo];
            }
        }
        __syncthreads();

        // ---------- phase B ----------
        if (w == 13) {
            // leader: 32 sequential steps, barrier-free
            for (int pp = 0; pp < BW; pp++) {
                int t = T0 + pp;
                // C_den @ q[t] via broadcast LDS of shq (stored last step)
                const float4* qv = (const float4*)shq;
                float4 q0 = qv[0], q1 = qv[1], q2 = qv[2], q3 = qv[3], q4 = qv[4];
                float a0 = 0, a1 = 0, a2 = 0, a3 = 0;
                a0 = fmaf(cd[0],  q0.x, a0); a1 = fmaf(cd[1],  q0.y, a1);
                a2 = fmaf(cd[2],  q0.z, a2); a3 = fmaf(cd[3],  q0.w, a3);
                a0 = fmaf(cd[4],  q1.x, a0); a1 = fmaf(cd[5],  q1.y, a1);
                a2 = fmaf(cd[6],  q1.z, a2); a3 = fmaf(cd[7],  q1.w, a3);
                a0 = fmaf(cd[8],  q2.x, a0); a1 = fmaf(cd[9],  q2.y, a1);
                a2 = fmaf(cd[10], q2.z, a2); a3 = fmaf(cd[11], q2.w, a3);
                a0 = fmaf(cd[12], q3.x, a0); a1 = fmaf(cd[13], q3.y, a1);
                a2 = fmaf(cd[14], q3.z, a2); a3 = fmaf(cd[15], q3.w, a3);
                a0 = fmaf(cd[16], q4.x, a0); a1 = fmaf(cd[17], q4.y, a1);
                a2 = fmaf(cd[18], q4.z, a2); a3 = fmaf(cd[19], q4.w, a3);

                if (lane < SUBN) {
                    U = fmaf(rr, U, zfprev);      // u[t] from z[t-1]
                    V = rr * (V + U);             // v[t+1]
                    const float* lp = &lut[lane * LPITCH];
                    float sv = Etot[pp * EPITCH + lane];
                    sv += lp[        (zmask & 255u)];
                    sv += lp[256 + ((zmask >> 8)  & 255u)];
                    sv += lp[512 + ((zmask >> 16) & 255u)];
                    sv += lp[768 +  (zmask >> 24)];
                    sv += (a0 + a1) + (a2 + a3);
                    float zf = (sv > 0.0f) ? 1.0f : 0.0f;
                    if (t < T_DATA) g_sv[t * SUBN + lane] = sv;
                    zmask  = (zmask << 1) | (sv > 0.0f ? 1u : 0u);
                    zfprev = zf;
                    shq[lane] = cc * V;           // publish q[t+1]
                }
                __syncwarp();
            }
            // publish this block's spike word
            if (lane < SUBN) bwr[lane * BWPITCH + (blk & 15)] = zmask;
        } else {
            // prefetch next-block syn rows into registers (MLP-hidden)
            float pf0 = 0.0f, pf1 = 0.0f, pf2 = 0.0f;
            if (lane < SUBN) {
                int tg0 = T0 + BW + r0;
                int tg1 = T0 + BW + r1;
                pf0 = (tg0 < T_DATA) ? g_syn[tg0 * SUBN + lane] : 0.0f;
                pf1 = (tg1 < T_DATA) ? g_syn[tg1 * SUBN + lane] : 0.0f;
                if (r2 < BW) {
                    int tg2 = T0 + BW + r2;
                    pf2 = (tg2 < T_DATA) ? g_syn[tg2 * SUBN + lane] : 0.0f;
                }
            }

            // far taps m=64..199 (i=16..49) for NEXT block; uses words <= blk-1
            for (int pass = w; pass < SUBN; pass += 13) {
                int s = pass;
                const unsigned* bb = &bwr[s * BWPITCH];
                unsigned v0 = bb[(blk - 1) & 15];
                unsigned v1 = bb[(blk - 2) & 15];
                unsigned v2 = bb[(blk - 3) & 15];
                unsigned v3 = bb[(blk - 4) & 15];
                unsigned v4 = bb[(blk - 5) & 15];
                unsigned v5 = bb[(blk - 6) & 15];
                unsigned v6 = bb[(blk - 7) & 15];
                unsigned w0 = o ? v1 : v0;
                unsigned w1 = o ? v2 : v1;
                unsigned w2 = o ? v3 : v2;
                unsigned w3 = o ? v4 : v3;
                unsigned w4 = o ? v5 : v4;
                unsigned w5 = o ? v6 : v5;
                unsigned aw0 = __funnelshift_r(w0, w1, sh);
                unsigned aw1 = __funnelshift_r(w1, w2, sh);
                unsigned aw2 = __funnelshift_r(w2, w3, sh);
                unsigned aw3 = __funnelshift_r(w3, w4, sh);
                unsigned aw4 = __funnelshift_r(w4, w5, sh);
                const float* lp = &lutn[s * NPITCH + 16 * 16];
                float b0 = 0, b1 = 0, b2 = 0, b3 = 0;
                #pragma unroll
                for (int ii = 0; ii < 34; ii++) {
                    unsigned word = (ii < 8) ? aw0 : (ii < 16) ? aw1 :
                                    (ii < 24) ? aw2 : (ii < 32) ? aw3 : aw4;
                    unsigned nib = (word >> (4 * (ii & 7))) & 15u;
                    float v = lp[ii * 16 + nib];
                    if ((ii & 3) == 0) b0 += v;
                    else if ((ii & 3) == 1) b1 += v;
                    else if ((ii & 3) == 2) b2 += v;
                    else b3 += v;
                }
                Hfar[p * EPITCH + s] = (b0 + b1) + (b2 + b3);
            }

            // store staged rows (phase A of this block already consumed synb)
            if (lane < SUBN) {
                synb[r0 * EPITCH + lane] = pf0;
                synb[r1 * EPITCH + lane] = pf1;
                if (r2 < BW) synb[r2 * EPITCH + lane] = pf2;
            }
        }
        __syncthreads();
    }
}

// ---------------- K4: Z/P from raw pre-activations ----------------
__global__ void zp_kernel(float* __restrict__ Z, float* __restrict__ P)
{
    int idx = blockIdx.x * blockDim.x + threadIdx.x;
    if (idx < T_DATA * SUBN) {
        float sv = g_sv[idx];
        Z[idx] = (sv > 0.0f) ? 1.0f : 0.0f;
        P[idx] = 1.0f / (1.0f + expf(-sv));
    }
}

// ---------------- launch ----------------
extern "C" void kernel_launch(void* const* d_in, const int* in_sizes, int n_in,
                              void* d_out, int out_size)
{
    const float* S_e       = (const float*)d_in[0];
    const float* S_i       = (const float*)d_in[1];
    const float* C_den     = (const float*)d_in[2];
    const float* C_syn_e   = (const float*)d_in[3];
    const float* C_syn_i   = (const float*)d_in[4];
    const float* Tau_syn   = (const float*)d_in[5];
    const float* Delta_syn = (const float*)d_in[6];
    const float* W_syn     = (const float*)d_in[7];
    const float* Tau_spk   = (const float*)d_in[8];
    const float* W_spk     = (const float*)d_in[9];
    const float* W_hist    = (const float*)d_in[10];
    const float* Theta     = (const float*)d_in[11];

    float* out = (float*)d_out;
    float* Z = out;                          // [10000, 20]
    float* P = out + T_DATA * SUBN;          // [10000, 20]
    float* F = out + 2 * T_DATA * SUBN;      // [80, 200]

    prep_kernel<<<1, 256>>>(C_syn_e, C_syn_i, Tau_syn, Delta_syn, W_syn,
                            Tau_spk, W_spk, W_hist, F);
    agg_kernel<<<T_DATA, 256>>>(S_e, S_i);

    cudaFuncSetAttribute(conv_kernel,
                         cudaFuncAttributeMaxDynamicSharedMemorySize,
                         CONV_SMEM_FLOATS * (int)sizeof(float));
    conv_kernel<<<(T_DATA + CONV_TS - 1) / CONV_TS, CONV_THREADS,
                  CONV_SMEM_FLOATS * sizeof(float)>>>(Theta);

    cudaFuncSetAttribute(recur_kernel,
                         cudaFuncAttributeMaxDynamicSharedMemorySize,
                         RECUR_SMEM_FLOATS * (int)sizeof(float));
    recur_kernel<<<1, RECUR_THREADS, RECUR_SMEM_FLOATS * sizeof(float)>>>(
        C_den, Tau_spk, W_spk);

    zp_kernel<<<(T_DATA * SUBN + 255) / 256, 256>>>(Z, P);
}